// round 6
// baseline (speedup 1.0000x reference)
#include <cuda_runtime.h>
#include <math.h>
#include <stdint.h>

// ---------------- problem constants ----------------------------------------
#define B_    1024
#define DIM_  512
#define C_    1000
#define N_    8
#define CN_   8000
#define CNP_  8064
#define CP_   1024
#define NEED_ 392       // topk(400) = 8 always-selected positives + top-392 others
#define WLAMBDA 0.3
#define CAP_  1024

// ---------------- scratch (device globals) ----------------------------------
__device__ float4 g_xrA[(size_t)(B_ / 16) * 64 * 8 * 4];
__device__ float4 g_pTA[(size_t)(CNP_ / 16) * 64 * 8 * 4];
__device__ float4 g_pTB[(size_t)(CNP_ / 8) * 64 * 8 * 2];
__device__ float4 g_ccB[(size_t)(CP_ / 8) * 64 * 8 * 2];
__device__ float  g_sim[(size_t)B_ * CN_];
__device__ float  g_pmax[CN_ * 8];
__device__ float  g_psum[CN_ * 8];
__device__ float  g_diag[CN_];
__device__ double g_acc[2];

// ---------------- helpers ----------------------------------------------------
__device__ __forceinline__ float tf32r(float f) {
    uint32_t r;
    asm("cvt.rna.tf32.f32 %0, %1;" : "=r"(r) : "f"(f));
    return __uint_as_float(r);
}
__device__ __forceinline__ uint32_t smem_u32(const void* p) {
    uint32_t a;
    asm("{ .reg .u64 t; cvta.to.shared.u64 t, %1; cvt.u32.u64 %0, t; }" : "=r"(a) : "l"(p));
    return a;
}
__device__ __forceinline__ void cpa16(uint32_t dst, const void* src) {
    uint64_t g = __cvta_generic_to_global(src);
    asm volatile("cp.async.cg.shared.global [%0], [%1], 16;" :: "r"(dst), "l"(g));
}
#define CP_COMMIT() asm volatile("cp.async.commit_group;" ::: "memory")

__device__ __forceinline__ void mma_tf32(float* c, const uint32_t* a, const uint32_t* b) {
    asm volatile(
        "mma.sync.aligned.m16n8k8.row.col.f32.tf32.tf32.f32 "
        "{%0,%1,%2,%3}, {%4,%5,%6,%7}, {%8,%9}, {%0,%1,%2,%3};"
        : "+f"(c[0]), "+f"(c[1]), "+f"(c[2]), "+f"(c[3])
        : "r"(a[0]), "r"(a[1]), "r"(a[2]), "r"(a[3]), "r"(b[0]), "r"(b[1]));
}
__device__ __forceinline__ unsigned key_of(float v) {
    unsigned u = __float_as_uint(v);
    return (u & 0x80000000u) ? ~u : (u | 0x80000000u);
}
__device__ __forceinline__ float key_inv(unsigned k) {
    unsigned u = (k & 0x80000000u) ? (k & 0x7FFFFFFFu) : ~k;
    return __uint_as_float(u);
}

// ---------------- prep: x -> A-layout ----------------------------------------
__global__ void __launch_bounds__(256) prep_x(const float* __restrict__ x) {
    __shared__ float xs[16][516];
    int g = blockIdx.x, tid = threadIdx.x;
    if (g == 0 && tid < 2) g_acc[tid] = 0.0;

    const float4* x4 = (const float4*)x;
    #pragma unroll
    for (int e = 0; e < 8; e++) {
        int lin = e * 256 + tid;
        int row = lin >> 7, kf = lin & 127;
        float4 v = x4[(size_t)(g * 16 + row) * 128 + kf];
        xs[row][kf * 4 + 0] = v.x; xs[row][kf * 4 + 1] = v.y;
        xs[row][kf * 4 + 2] = v.z; xs[row][kf * 4 + 3] = v.w;
    }
    __syncthreads();
    #pragma unroll
    for (int e = 0; e < 8; e++) {
        int lin = e * 256 + tid;
        int ksG = lin >> 5, q = (lin >> 2) & 7, lc = lin & 3;
        int k = ksG * 8 + lc;
        float4 o;
        o.x = tf32r(xs[q][k]);     o.y = tf32r(xs[q + 8][k]);
        o.z = tf32r(xs[q][k + 4]); o.w = tf32r(xs[q + 8][k + 4]);
        g_xrA[((size_t)g * 64 + ksG) * 32 + q * 4 + lc] = o;
    }
}

// ---------------- prep: proxies -> norms, pTA, pTB, ccB ----------------------
__global__ void __launch_bounds__(256) prep_prox(const float* __restrict__ proxies) {
    __shared__ float red[8][32];
    __shared__ float sinv[32];
    int j0 = blockIdx.x * 32, tid = threadIdx.x;
    int jj = tid & 31, ds = tid >> 5;

    float acc = 0.f;
    for (int d = ds; d < DIM_; d += 8) {
        float v = proxies[(size_t)d * CN_ + j0 + jj];
        acc += v * v;
    }
    red[ds][jj] = acc;
    __syncthreads();
    if (ds == 0) {
        float s = 0.f;
        #pragma unroll
        for (int i = 0; i < 8; i++) s += red[i][jj];
        sinv[jj] = 1.0f / fmaxf(sqrtf(s), 1e-12f);
    }
    __syncthreads();

    #pragma unroll
    for (int e = 0; e < 16; e++) {
        int lin = e * 256 + tid;
        int gl = lin >> 11, ksG = (lin >> 5) & 63, q = (lin >> 2) & 7, lc = lin & 3;
        int jA = j0 + gl * 16 + q;
        int d = ksG * 8 + lc;
        float4 o;
        o.x = tf32r(proxies[(size_t)d * CN_ + jA] * sinv[jA - j0]);
        o.y = tf32r(proxies[(size_t)d * CN_ + jA + 8] * sinv[jA + 8 - j0]);
        o.z = tf32r(proxies[(size_t)(d + 4) * CN_ + jA] * sinv[jA - j0]);
        o.w = tf32r(proxies[(size_t)(d + 4) * CN_ + jA + 8] * sinv[jA + 8 - j0]);
        g_pTA[((size_t)(j0 / 16 + gl) * 64 + ksG) * 32 + q * 4 + lc] = o;
    }

    #pragma unroll
    for (int e = 0; e < 16; e++) {
        int lin = e * 256 + tid;
        int glB = lin >> 10, ksG = (lin >> 4) & 63, qB = (lin >> 1) & 7, p = lin & 1;
        int j = j0 + glB * 8 + qB;
        int k0 = ksG * 8 + 2 * p;
        float iv = sinv[j - j0];
        float4 o;
        o.x = tf32r(proxies[(size_t)k0 * CN_ + j] * iv);
        o.y = tf32r(proxies[(size_t)(k0 + 4) * CN_ + j] * iv);
        o.z = tf32r(proxies[(size_t)(k0 + 1) * CN_ + j] * iv);
        o.w = tf32r(proxies[(size_t)(k0 + 5) * CN_ + j] * iv);
        g_pTB[((size_t)(j0 / 8 + glB) * 64 + ksG) * 16 + qB * 2 + p] = o;
    }

    #pragma unroll
    for (int e = 0; e < 2; e++) {
        int lin = e * 256 + tid;
        int cl = lin >> 7, ksG = (lin >> 1) & 63, p = lin & 1;
        int c = j0 / 8 + cl;
        int gB = c >> 3, qB = c & 7;
        int k0 = ksG * 8 + 2 * p;
        float s0 = 0.f, s1 = 0.f, s2 = 0.f, s3 = 0.f;
        #pragma unroll
        for (int n = 0; n < 8; n++) {
            int j = c * 8 + n;
            float iv = sinv[j - j0];
            s0 += proxies[(size_t)k0 * CN_ + j] * iv;
            s1 += proxies[(size_t)(k0 + 4) * CN_ + j] * iv;
            s2 += proxies[(size_t)(k0 + 1) * CN_ + j] * iv;
            s3 += proxies[(size_t)(k0 + 5) * CN_ + j] * iv;
        }
        float4 o = make_float4(tf32r(s0), tf32r(s1), tf32r(s2), tf32r(s3));
        g_ccB[((size_t)gB * 64 + ksG) * 16 + qB * 2 + p] = o;
    }
}

// ---------------- merged tf32 mma.sync GEMM (3-stage, 2 CTA/SM) -------------
// mode 0 (bid<504):  g_sim = x @ centers, stored
// mode 1 (bid>=504): centers^T @ ccls -> per-row lse partials + diag (no store)
#define NCHUNK 16
#define STG 32768
#define DYN_SMEM (3 * STG)

__global__ void __launch_bounds__(256, 2) gemm_all() {
    extern __shared__ char sh[];
    __shared__ unsigned smx[128];
    __shared__ float    ssm[128];

    int bid = blockIdx.x;
    const float4 *Ag, *Bg;
    int bm, bn;
    bool mode1 = (bid >= 504);
    if (!mode1) {
        Ag = g_xrA; Bg = g_pTB;
        bn = (bid % 63) * 128; bm = (bid / 63) * 128;
    } else {
        int b2 = bid - 504;
        Ag = g_pTA; Bg = g_ccB;
        bn = (b2 & 7) * 128; bm = (b2 >> 3) * 128;
    }
    int tid = threadIdx.x, wid = tid >> 5, lane = tid & 31;
    int lr = lane >> 2, lc4 = lane & 3;
    uint32_t sb = smem_u32(sh);
    int GA0 = bm / 16, GB0 = bn / 8;

    auto load_stage = [&](int ch, int s) {
        uint32_t stage = sb + (uint32_t)s * STG;
        #pragma unroll
        for (int e = 0; e < 8; e++) {
            int lin = e * 256 + tid;
            if (lin < 1024) {
                int ks = lin >> 8, g = (lin >> 5) & 7, q = (lin >> 2) & 7, lc = lin & 3;
                cpa16(stage + (uint32_t)lin * 16,
                      Ag + ((size_t)(GA0 + g) * 64 + ch * 4 + ks) * 32 + q * 4 + lc);
            } else {
                int l2 = lin - 1024;
                int ks = l2 >> 8, gB = (l2 >> 4) & 15, qB = (l2 >> 1) & 7, p = l2 & 1;
                cpa16(stage + 16384u + (uint32_t)l2 * 16,
                      Bg + ((size_t)(GB0 + gB) * 64 + ch * 4 + ks) * 16 + qB * 2 + p);
            }
        }
        CP_COMMIT();
    };

    load_stage(0, 0);
    load_stage(1, 1);

    int ga = (wid >> 2) * 4;
    int gb = (wid & 3) * 4;

    float c[4][4][4];
    #pragma unroll
    for (int mt = 0; mt < 4; mt++)
        #pragma unroll
        for (int nt = 0; nt < 4; nt++)
            #pragma unroll
            for (int i = 0; i < 4; i++) c[mt][nt][i] = 0.f;

    for (int ch = 0; ch < NCHUNK; ch++) {
        if (ch < NCHUNK - 1) asm volatile("cp.async.wait_group 1;" ::: "memory");
        else                 asm volatile("cp.async.wait_group 0;" ::: "memory");
        __syncthreads();

        if (ch + 2 < NCHUNK) load_stage(ch + 2, (ch + 2) % 3);

        const float4* As = (const float4*)(sh + (ch % 3) * STG);
        const float2* Bs = (const float2*)(sh + (ch % 3) * STG + 16384);

        #pragma unroll
        for (int ks = 0; ks < 4; ks++) {
            uint32_t a[4][4], b[4][2];
            #pragma unroll
            for (int mt = 0; mt < 4; mt++) {
                float4 v = As[((ks * 8 + ga + mt) * 8 + lr) * 4 + lc4];
                a[mt][0] = __float_as_uint(v.x); a[mt][1] = __float_as_uint(v.y);
                a[mt][2] = __float_as_uint(v.z); a[mt][3] = __float_as_uint(v.w);
            }
            #pragma unroll
            for (int nt = 0; nt < 4; nt++) {
                float2 v = Bs[((ks * 16 + gb + nt) * 8 + lr) * 4 + lc4];
                b[nt][0] = __float_as_uint(v.x); b[nt][1] = __float_as_uint(v.y);
            }
            #pragma unroll
            for (int mt = 0; mt < 4; mt++)
                #pragma unroll
                for (int nt = 0; nt < 4; nt++)
                    mma_tf32(c[mt][nt], a[mt], b[nt]);
        }
    }

    int wm = (wid >> 2) * 64, wn = (wid & 3) * 32;

    if (!mode1) {
        // store sim tile (full tile always in-bounds: 1024x8064 covers, cols<8000 guard)
        #pragma unroll
        for (int mt = 0; mt < 4; mt++) {
            int row = bm + wm + mt * 16 + lr;
            #pragma unroll
            for (int nt = 0; nt < 4; nt++) {
                int col = bn + wn + nt * 8 + lc4 * 2;
                if (col < CN_) {
                    *(float2*)(g_sim + (size_t)row * CN_ + col) = make_float2(c[mt][nt][0], c[mt][nt][1]);
                    *(float2*)(g_sim + (size_t)(row + 8) * CN_ + col) = make_float2(c[mt][nt][2], c[mt][nt][3]);
                }
            }
        }
        return;
    }

    // ---- mode 1: per-row (max, sum-exp) partials over this 128-col tile ----
    bool v0[4], v1[4];
    #pragma unroll
    for (int nt = 0; nt < 4; nt++) {
        int col0 = bn + wn + nt * 8 + lc4 * 2;
        v0[nt] = (col0 < C_);
        v1[nt] = (col0 + 1 < C_);
    }

    if (tid < 128) { smx[tid] = key_of(-3.0e38f); ssm[tid] = 0.f; }
    __syncthreads();

    #pragma unroll
    for (int mt = 0; mt < 4; mt++) {
        int rl0 = wm + mt * 16 + lr, rl1 = rl0 + 8;
        float m0 = -3.0e38f, m1 = -3.0e38f;
        #pragma unroll
        for (int nt = 0; nt < 4; nt++) {
            if (v0[nt]) { m0 = fmaxf(m0, c[mt][nt][0]); m1 = fmaxf(m1, c[mt][nt][2]); }
            if (v1[nt]) { m0 = fmaxf(m0, c[mt][nt][1]); m1 = fmaxf(m1, c[mt][nt][3]); }
        }
        atomicMax(&smx[rl0], key_of(m0));
        atomicMax(&smx[rl1], key_of(m1));
    }
    __syncthreads();

    #pragma unroll
    for (int mt = 0; mt < 4; mt++) {
        int rl0 = wm + mt * 16 + lr, rl1 = rl0 + 8;
        int gr0 = bm + rl0, gr1 = bm + rl1;
        float m0 = key_inv(smx[rl0]), m1 = key_inv(smx[rl1]);
        float s0 = 0.f, s1 = 0.f;
        #pragma unroll
        for (int nt = 0; nt < 4; nt++) {
            int col0 = bn + wn + nt * 8 + lc4 * 2;
            if (v0[nt]) {
                s0 += __expf(c[mt][nt][0] - m0);
                s1 += __expf(c[mt][nt][2] - m1);
                if (col0 == (gr0 >> 3) && gr0 < CN_) g_diag[gr0] = c[mt][nt][0];
                if (col0 == (gr1 >> 3) && gr1 < CN_) g_diag[gr1] = c[mt][nt][2];
            }
            if (v1[nt]) {
                s0 += __expf(c[mt][nt][1] - m0);
                s1 += __expf(c[mt][nt][3] - m1);
                if (col0 + 1 == (gr0 >> 3) && gr0 < CN_) g_diag[gr0] = c[mt][nt][1];
                if (col0 + 1 == (gr1 >> 3) && gr1 < CN_) g_diag[gr1] = c[mt][nt][3];
            }
        }
        atomicAdd(&ssm[rl0], s0);
        atomicAdd(&ssm[rl1], s1);
    }
    __syncthreads();

    if (tid < 128) {
        int gr = bm + tid;
        if (gr < CN_) {
            g_pmax[gr * 8 + (bn >> 7)] = key_inv(smx[tid]);
            g_psum[gr * 8 + (bn >> 7)] = ssm[tid];
        }
    }
}

// ---------------- epilogue: topk+loss (blocks 0..1023), lse combine (rest) ---
__global__ void __launch_bounds__(256) epilogue_kernel(const int* __restrict__ target) {
    __shared__ unsigned short key16[CN_];
    __shared__ unsigned hist[2048];
    __shared__ unsigned candk[CAP_];
    __shared__ unsigned short candj[CAP_];
    __shared__ float    cls[C_];
    __shared__ unsigned uns[8];
    __shared__ float    wsum[8];
    __shared__ float    s_pos;
    __shared__ unsigned sh_bin, sh_need, sh_cnt;

    int tid = threadIdx.x;
    int wid = tid >> 5, lane = tid & 31;

    if (blockIdx.x >= B_) {
        // ---- combine lse partials: one row per thread ----
        int row = (int)(blockIdx.x - B_) * 256 + tid;
        float regv = 0.f;
        if (row < CN_) {
            float M = -3.0e38f;
            #pragma unroll
            for (int t = 0; t < 8; t++) M = fmaxf(M, g_pmax[row * 8 + t]);
            float S = 0.f;
            #pragma unroll
            for (int t = 0; t < 8; t++)
                S += g_psum[row * 8 + t] * __expf(g_pmax[row * 8 + t] - M);
            regv = M + __logf(S) - g_diag[row];
        }
        #pragma unroll
        for (int o = 16; o > 0; o >>= 1) regv += __shfl_xor_sync(0xffffffffu, regv, o);
        if (lane == 0 && regv != 0.f) atomicAdd(&g_acc[1], (double)regv);
        return;
    }

    // ---- topk + classification loss, one row per block ----
    int b = blockIdx.x;
    const float4* row4 = (const float4*)(g_sim + (size_t)b * CN_);
    int tgt = target[b];

    for (int c = tid; c < C_; c += 256) cls[c] = 0.f;
    for (int i = tid; i < 2048; i += 256) hist[i] = 0;
    if (tid == 0) { s_pos = 0.f; sh_cnt = 0; }
    __syncthreads();

    // pass A: cache 16-bit key prefixes + level-0 histogram + positive sum
    float pos = 0.f;
    for (int i = tid; i < CN_ / 4; i += 256) {
        float4 v = row4[i];
        int j = i * 4;
        if ((i >> 1) == tgt) {
            pos += v.x + v.y + v.z + v.w;
            key16[j] = 0; key16[j + 1] = 0; key16[j + 2] = 0; key16[j + 3] = 0;
        } else {
            unsigned k0 = key_of(v.x), k1 = key_of(v.y), k2 = key_of(v.z), k3 = key_of(v.w);
            key16[j] = (unsigned short)(k0 >> 16);
            key16[j + 1] = (unsigned short)(k1 >> 16);
            key16[j + 2] = (unsigned short)(k2 >> 16);
            key16[j + 3] = (unsigned short)(k3 >> 16);
            atomicAdd(&hist[k0 >> 21], 1u);
            atomicAdd(&hist[k1 >> 21], 1u);
            atomicAdd(&hist[k2 >> 21], 1u);
            atomicAdd(&hist[k3 >> 21], 1u);
        }
    }
    if (pos != 0.f) atomicAdd(&s_pos, pos);
    __syncthreads();

    auto select_bin = [&](int nb, unsigned nd) {
        int nch = nb >> 3;
        unsigned chunk = 0;
        if (tid < nch) {
            int base = tid * 8;
            #pragma unroll
            for (int i = 0; i < 8; i++) chunk += hist[base + i];
        }
        unsigned v = chunk;
        #pragma unroll
        for (int off = 1; off < 32; off <<= 1) {
            unsigned t = __shfl_down_sync(0xffffffffu, v, off);
            if (lane + off < 32) v += t;
        }
        if (lane == 0) uns[wid] = v;
        __syncthreads();
        unsigned woff = 0;
        for (int w = wid + 1; w < 8; w++) woff += uns[w];
        unsigned Sincl = v + woff;
        unsigned Saft = Sincl - chunk;
        if (tid < nch && Saft < nd && Sincl >= nd) {
            unsigned cum = Saft;
            int bb = tid * 8 + 7;
            while (cum + hist[bb] < nd) { cum += hist[bb]; bb--; }
            sh_bin = (unsigned)bb;
            sh_need = nd - cum;
        }
        __syncthreads();
    };

    // level 0: 2048 bins over key16>>5
    select_bin(2048, NEED_);
    unsigned p0 = sh_bin;
    unsigned need = sh_need;
    __syncthreads();

    // level 1: 32 bins over key16&31, restricted to prefix p0 (smem only)
    for (int i = tid; i < 32; i += 256) hist[i] = 0;
    __syncthreads();
    for (int j = tid; j < CN_; j += 256) {
        unsigned k16 = key16[j];
        if ((k16 >> 5) == p0) atomicAdd(&hist[k16 & 31u], 1u);
    }
    __syncthreads();
    select_bin(32, need);
    unsigned p16 = (p0 << 5) | sh_bin;   // full 16-bit boundary prefix
    need = sh_need;
    __syncthreads();

    // pass B: accumulate sure-included keys, gather boundary candidates
    for (int i = tid; i < CN_ / 4; i += 256) {
        if ((i >> 1) == tgt) continue;
        int j = i * 4;
        unsigned a0 = key16[j], a1 = key16[j + 1], a2 = key16[j + 2], a3 = key16[j + 3];
        unsigned mx = max(max(a0, a1), max(a2, a3));
        if (mx < p16) continue;
        float4 v = row4[i];
        float add = 0.f;
        if (a0 > p16) add += v.x;
        else if (a0 == p16) { unsigned q = atomicAdd(&sh_cnt, 1u); if (q < CAP_) { candk[q] = key_of(v.x); candj[q] = (unsigned short)j; } }
        if (a1 > p16) add += v.y;
        else if (a1 == p16) { unsigned q = atomicAdd(&sh_cnt, 1u); if (q < CAP_) { candk[q] = key_of(v.y); candj[q] = (unsigned short)(j + 1); } }
        if (a2 > p16) add += v.z;
        else if (a2 == p16) { unsigned q = atomicAdd(&sh_cnt, 1u); if (q < CAP_) { candk[q] = key_of(v.z); candj[q] = (unsigned short)(j + 2); } }
        if (a3 > p16) add += v.w;
        else if (a3 == p16) { unsigned q = atomicAdd(&sh_cnt, 1u); if (q < CAP_) { candk[q] = key_of(v.w); candj[q] = (unsigned short)(j + 3); } }
        if (add != 0.f) atomicAdd(&cls[i >> 1], add);
    }
    __syncthreads();
    unsigned cnt = min(sh_cnt, (unsigned)CAP_);

    // exact select among candidates: bits [15:5] then [4:0]
    for (int i = tid; i < 2048; i += 256) hist[i] = 0;
    __syncthreads();
    for (unsigned i = tid; i < cnt; i += 256)
        atomicAdd(&hist[(candk[i] >> 5) & 2047u], 1u);
    __syncthreads();
    select_bin(2048, need);
    unsigned b1 = sh_bin;
    need = sh_need;
    __syncthreads();
    for (int i = tid; i < 32; i += 256) hist[i] = 0;
    __syncthreads();
    for (unsigned i = tid; i < cnt; i += 256) {
        unsigned k = candk[i];
        if (((k >> 5) & 2047u) == b1) atomicAdd(&hist[k & 31u], 1u);
    }
    __syncthreads();
    select_bin(32, need);
    unsigned T = (p16 << 16) | (b1 << 5) | sh_bin;  // exact 392nd-largest key
    __syncthreads();

    // add boundary candidates >= T
    for (unsigned i = tid; i < cnt; i += 256) {
        unsigned k = candk[i];
        if (k >= T) atomicAdd(&cls[candj[i] >> 3], key_inv(k));
    }
    __syncthreads();
    if (tid == 0) cls[tgt] += s_pos;
    __syncthreads();

    // masked softmax loss
    float lsum = 0.f;
    for (int c = tid; c < C_; c += 256) {
        float l = cls[c];
        if (l != 0.0f) lsum += __expf(l);
    }
    #pragma unroll
    for (int o = 16; o > 0; o >>= 1) lsum += __shfl_xor_sync(0xffffffffu, lsum, o);
    if (lane == 0) wsum[wid] = lsum;
    __syncthreads();
    if (tid == 0) {
        float tot = 0.f;
        #pragma unroll
        for (int w = 0; w < 8; w++) tot += wsum[w];
        float lt = cls[tgt];
        float num = (lt != 0.0f) ? __expf(lt) : 0.0f;
        float pr = num / (1e-8f + tot);
        atomicAdd(&g_acc[0], (double)(-__logf(pr + 1e-20f)));
    }
}

// ---------------- finalize ---------------------------------------------------
__global__ void finalize_kernel(float* out, int out_size) {
    double lc = g_acc[0] / (double)B_;
    double rg = g_acc[1] / (double)CN_;
    out[0] = (float)(lc + WLAMBDA * rg);
    if (out_size > 1) out[1] = (float)lc;
}

// ---------------- launch -----------------------------------------------------
extern "C" void kernel_launch(void* const* d_in, const int* in_sizes, int n_in,
                              void* d_out, int out_size) {
    const float* x       = (const float*)d_in[0];
    const float* proxies = (const float*)d_in[1];
    const int*   target  = (const int*)d_in[2];
    float* out = (float*)d_out;

    cudaFuncSetAttribute(gemm_all, cudaFuncAttributeMaxDynamicSharedMemorySize, DYN_SMEM);

    prep_x<<<B_ / 16, 256>>>(x);
    prep_prox<<<CN_ / 32, 256>>>(proxies);
    gemm_all<<<1008, 256, DYN_SMEM>>>();
    epilogue_kernel<<<B_ + (CN_ + 255) / 256, 256>>>(target);
    finalize_kernel<<<1, 1>>>(out, out_size);
}

// round 7
// speedup vs baseline: 1.0660x; 1.0660x over previous
#include <cuda_runtime.h>
#include <math.h>
#include <stdint.h>

// ---------------- problem constants ----------------------------------------
#define B_    1024
#define DIM_  512
#define C_    1000
#define N_    8
#define CN_   8000
#define CNP_  8064
#define CP_   1024
#define NEED_ 392
#define WLAMBDA 0.3

// ---------------- scratch (device globals) ----------------------------------
__device__ float4 g_xrA[(size_t)(B_ / 16) * 64 * 8 * 4];
__device__ float4 g_pTA[(size_t)(CNP_ / 16) * 64 * 8 * 4];
__device__ float4 g_pTB[(size_t)(CNP_ / 8) * 64 * 8 * 2];
__device__ float4 g_ccB[(size_t)(CP_ / 8) * 64 * 8 * 2];
__device__ float  g_sim[(size_t)B_ * CN_];
__device__ float  g_pmax[CN_ * 8];
__device__ float  g_psum[CN_ * 8];
__device__ float  g_diag[CN_];
__device__ double g_acc[2];

// ---------------- helpers ----------------------------------------------------
__device__ __forceinline__ float tf32r(float f) {
    uint32_t r;
    asm("cvt.rna.tf32.f32 %0, %1;" : "=r"(r) : "f"(f));
    return __uint_as_float(r);
}
__device__ __forceinline__ uint32_t smem_u32(const void* p) {
    uint32_t a;
    asm("{ .reg .u64 t; cvta.to.shared.u64 t, %1; cvt.u32.u64 %0, t; }" : "=r"(a) : "l"(p));
    return a;
}
__device__ __forceinline__ void cpa16(uint32_t dst, const void* src) {
    uint64_t g = __cvta_generic_to_global(src);
    asm volatile("cp.async.cg.shared.global [%0], [%1], 16;" :: "r"(dst), "l"(g));
}
#define CP_COMMIT() asm volatile("cp.async.commit_group;" ::: "memory")

__device__ __forceinline__ void mma_tf32(float* c, const uint32_t* a, const uint32_t* b) {
    asm volatile(
        "mma.sync.aligned.m16n8k8.row.col.f32.tf32.tf32.f32 "
        "{%0,%1,%2,%3}, {%4,%5,%6,%7}, {%8,%9}, {%0,%1,%2,%3};"
        : "+f"(c[0]), "+f"(c[1]), "+f"(c[2]), "+f"(c[3])
        : "r"(a[0]), "r"(a[1]), "r"(a[2]), "r"(a[3]), "r"(b[0]), "r"(b[1]));
}
__device__ __forceinline__ unsigned key_of(float v) {
    unsigned u = __float_as_uint(v);
    return (u & 0x80000000u) ? ~u : (u | 0x80000000u);
}

// ---------------- prep: x -> A-layout ----------------------------------------
__global__ void __launch_bounds__(256) prep_x(const float* __restrict__ x) {
    __shared__ float xs[16][516];
    int g = blockIdx.x, tid = threadIdx.x;
    if (g == 0 && tid < 2) g_acc[tid] = 0.0;

    const float4* x4 = (const float4*)x;
    #pragma unroll
    for (int e = 0; e < 8; e++) {
        int lin = e * 256 + tid;
        int row = lin >> 7, kf = lin & 127;
        float4 v = x4[(size_t)(g * 16 + row) * 128 + kf];
        xs[row][kf * 4 + 0] = v.x; xs[row][kf * 4 + 1] = v.y;
        xs[row][kf * 4 + 2] = v.z; xs[row][kf * 4 + 3] = v.w;
    }
    __syncthreads();
    #pragma unroll
    for (int e = 0; e < 8; e++) {
        int lin = e * 256 + tid;
        int ksG = lin >> 5, q = (lin >> 2) & 7, lc = lin & 3;
        int k = ksG * 8 + lc;
        float4 o;
        o.x = tf32r(xs[q][k]);     o.y = tf32r(xs[q + 8][k]);
        o.z = tf32r(xs[q][k + 4]); o.w = tf32r(xs[q + 8][k + 4]);
        g_xrA[((size_t)g * 64 + ksG) * 32 + q * 4 + lc] = o;
    }
}

// ---------------- prep: proxies -> norms, pTA, pTB, ccB ----------------------
__global__ void __launch_bounds__(256) prep_prox(const float* __restrict__ proxies) {
    __shared__ float red[8][32];
    __shared__ float sinv[32];
    int j0 = blockIdx.x * 32, tid = threadIdx.x;
    int jj = tid & 31, ds = tid >> 5;

    float acc = 0.f;
    for (int d = ds; d < DIM_; d += 8) {
        float v = proxies[(size_t)d * CN_ + j0 + jj];
        acc += v * v;
    }
    red[ds][jj] = acc;
    __syncthreads();
    if (ds == 0) {
        float s = 0.f;
        #pragma unroll
        for (int i = 0; i < 8; i++) s += red[i][jj];
        sinv[jj] = 1.0f / fmaxf(sqrtf(s), 1e-12f);
    }
    __syncthreads();

    #pragma unroll
    for (int e = 0; e < 16; e++) {
        int lin = e * 256 + tid;
        int gl = lin >> 11, ksG = (lin >> 5) & 63, q = (lin >> 2) & 7, lc = lin & 3;
        int jA = j0 + gl * 16 + q;
        int d = ksG * 8 + lc;
        float4 o;
        o.x = tf32r(proxies[(size_t)d * CN_ + jA] * sinv[jA - j0]);
        o.y = tf32r(proxies[(size_t)d * CN_ + jA + 8] * sinv[jA + 8 - j0]);
        o.z = tf32r(proxies[(size_t)(d + 4) * CN_ + jA] * sinv[jA - j0]);
        o.w = tf32r(proxies[(size_t)(d + 4) * CN_ + jA + 8] * sinv[jA + 8 - j0]);
        g_pTA[((size_t)(j0 / 16 + gl) * 64 + ksG) * 32 + q * 4 + lc] = o;
    }

    #pragma unroll
    for (int e = 0; e < 16; e++) {
        int lin = e * 256 + tid;
        int glB = lin >> 10, ksG = (lin >> 4) & 63, qB = (lin >> 1) & 7, p = lin & 1;
        int j = j0 + glB * 8 + qB;
        int k0 = ksG * 8 + 2 * p;
        float iv = sinv[j - j0];
        float4 o;
        o.x = tf32r(proxies[(size_t)k0 * CN_ + j] * iv);
        o.y = tf32r(proxies[(size_t)(k0 + 4) * CN_ + j] * iv);
        o.z = tf32r(proxies[(size_t)(k0 + 1) * CN_ + j] * iv);
        o.w = tf32r(proxies[(size_t)(k0 + 5) * CN_ + j] * iv);
        g_pTB[((size_t)(j0 / 8 + glB) * 64 + ksG) * 16 + qB * 2 + p] = o;
    }

    #pragma unroll
    for (int e = 0; e < 2; e++) {
        int lin = e * 256 + tid;
        int cl = lin >> 7, ksG = (lin >> 1) & 63, p = lin & 1;
        int c = j0 / 8 + cl;
        int gB = c >> 3, qB = c & 7;
        int k0 = ksG * 8 + 2 * p;
        float s0 = 0.f, s1 = 0.f, s2 = 0.f, s3 = 0.f;
        #pragma unroll
        for (int n = 0; n < 8; n++) {
            int j = c * 8 + n;
            float iv = sinv[j - j0];
            s0 += proxies[(size_t)k0 * CN_ + j] * iv;
            s1 += proxies[(size_t)(k0 + 4) * CN_ + j] * iv;
            s2 += proxies[(size_t)(k0 + 1) * CN_ + j] * iv;
            s3 += proxies[(size_t)(k0 + 5) * CN_ + j] * iv;
        }
        float4 o = make_float4(tf32r(s0), tf32r(s1), tf32r(s2), tf32r(s3));
        g_ccB[((size_t)gB * 64 + ksG) * 16 + qB * 2 + p] = o;
    }
}

// ---------------- merged tf32 mma.sync GEMM (3-stage, 2 CTA/SM) -------------
// mode 0 (bid<504): g_sim = x @ centers
// mode 1 (bid>=504): centers^T @ ccls -> smem tile -> row lse partials + diag
#define NCHUNK 16
#define STG 32768
#define DYN_SMEM (3 * STG)
#define TP 130

__global__ void __launch_bounds__(256, 2) gemm_all() {
    extern __shared__ char sh[];
    int bid = blockIdx.x;
    const float4 *Ag, *Bg;
    int bm, bn;
    bool mode1 = (bid >= 504);
    if (!mode1) {
        Ag = g_xrA; Bg = g_pTB;
        bn = (bid % 63) * 128; bm = (bid / 63) * 128;
    } else {
        int b2 = bid - 504;
        Ag = g_pTA; Bg = g_ccB;
        bn = (b2 & 7) * 128; bm = (b2 >> 3) * 128;
    }
    int tid = threadIdx.x, wid = tid >> 5, lane = tid & 31;
    int lr = lane >> 2, lc4 = lane & 3;
    uint32_t sb = smem_u32(sh);
    int GA0 = bm / 16, GB0 = bn / 8;

    auto load_stage = [&](int ch, int s) {
        uint32_t stage = sb + (uint32_t)s * STG;
        #pragma unroll
        for (int e = 0; e < 8; e++) {
            int lin = e * 256 + tid;
            if (lin < 1024) {
                int ks = lin >> 8, g = (lin >> 5) & 7, q = (lin >> 2) & 7, lc = lin & 3;
                cpa16(stage + (uint32_t)lin * 16,
                      Ag + ((size_t)(GA0 + g) * 64 + ch * 4 + ks) * 32 + q * 4 + lc);
            } else {
                int l2 = lin - 1024;
                int ks = l2 >> 8, gB = (l2 >> 4) & 15, qB = (l2 >> 1) & 7, p = l2 & 1;
                cpa16(stage + 16384u + (uint32_t)l2 * 16,
                      Bg + ((size_t)(GB0 + gB) * 64 + ch * 4 + ks) * 16 + qB * 2 + p);
            }
        }
        CP_COMMIT();
    };

    load_stage(0, 0);
    load_stage(1, 1);

    int ga = (wid >> 2) * 4;
    int gb = (wid & 3) * 4;

    float c[4][4][4];
    #pragma unroll
    for (int mt = 0; mt < 4; mt++)
        #pragma unroll
        for (int nt = 0; nt < 4; nt++)
            #pragma unroll
            for (int i = 0; i < 4; i++) c[mt][nt][i] = 0.f;

    for (int ch = 0; ch < NCHUNK; ch++) {
        if (ch < NCHUNK - 1) asm volatile("cp.async.wait_group 1;" ::: "memory");
        else                 asm volatile("cp.async.wait_group 0;" ::: "memory");
        __syncthreads();

        if (ch + 2 < NCHUNK) load_stage(ch + 2, (ch + 2) % 3);

        const float4* As = (const float4*)(sh + (ch % 3) * STG);
        const float2* Bs = (const float2*)(sh + (ch % 3) * STG + 16384);

        #pragma unroll
        for (int ks = 0; ks < 4; ks++) {
            uint32_t a[4][4], b[4][2];
            #pragma unroll
            for (int mt = 0; mt < 4; mt++) {
                float4 v = As[((ks * 8 + ga + mt) * 8 + lr) * 4 + lc4];
                a[mt][0] = __float_as_uint(v.x); a[mt][1] = __float_as_uint(v.y);
                a[mt][2] = __float_as_uint(v.z); a[mt][3] = __float_as_uint(v.w);
            }
            #pragma unroll
            for (int nt = 0; nt < 4; nt++) {
                float2 v = Bs[((ks * 16 + gb + nt) * 8 + lr) * 4 + lc4];
                b[nt][0] = __float_as_uint(v.x); b[nt][1] = __float_as_uint(v.y);
            }
            #pragma unroll
            for (int mt = 0; mt < 4; mt++)
                #pragma unroll
                for (int nt = 0; nt < 4; nt++)
                    mma_tf32(c[mt][nt], a[mt], b[nt]);
        }
    }

    int wm = (wid >> 2) * 64, wn = (wid & 3) * 32;

    if (!mode1) {
        #pragma unroll
        for (int mt = 0; mt < 4; mt++) {
            int row = bm + wm + mt * 16 + lr;
            #pragma unroll
            for (int nt = 0; nt < 4; nt++) {
                int col = bn + wn + nt * 8 + lc4 * 2;
                if (col < CN_) {
                    *(float2*)(g_sim + (size_t)row * CN_ + col) = make_float2(c[mt][nt][0], c[mt][nt][1]);
                    *(float2*)(g_sim + (size_t)(row + 8) * CN_ + col) = make_float2(c[mt][nt][2], c[mt][nt][3]);
                }
            }
        }
        return;
    }

    // ---- mode 1: dump accumulators to smem tile (register-neutral), then reduce ----
    __syncthreads();   // mainloop smem fully consumed
    float* tile = (float*)sh;
    #pragma unroll
    for (int mt = 0; mt < 4; mt++) {
        int r0 = wm + mt * 16 + lr;
        #pragma unroll
        for (int nt = 0; nt < 4; nt++) {
            int cc = wn + nt * 8 + lc4 * 2;
            *(float2*)&tile[r0 * TP + cc] = make_float2(c[mt][nt][0], c[mt][nt][1]);
            *(float2*)&tile[(r0 + 8) * TP + cc] = make_float2(c[mt][nt][2], c[mt][nt][3]);
        }
    }
    __syncthreads();

    {
        int r = tid >> 1, h = tid & 1;
        int gr = bm + r;
        int vcols = C_ - bn; if (vcols > 128) vcols = 128;
        int cA = h * 64;
        int cB = cA + 64; if (cB > vcols) cB = vcols;
        float m = -3.0e38f;
        for (int j = cA; j < cB; j++) m = fmaxf(m, tile[r * TP + j]);
        float s = 0.f;
        for (int j = cA; j < cB; j++) s += __expf(tile[r * TP + j] - m);
        float mo = __shfl_xor_sync(0xffffffffu, m, 1);
        float so = __shfl_xor_sync(0xffffffffu, s, 1);
        float M = fmaxf(m, mo);
        float S = s * __expf(m - M) + so * __expf(mo - M);
        if (h == 0 && gr < CN_) {
            g_pmax[gr * 8 + (bn >> 7)] = M;
            g_psum[gr * 8 + (bn >> 7)] = S;
            int cl = gr >> 3;
            if (cl >= bn && cl - bn < vcols) g_diag[gr] = tile[r * TP + (cl - bn)];
        }
    }
}

// ---------------- epilogue: topk+loss (blocks <1024), lse combine (rest) -----
__global__ void __launch_bounds__(256) epilogue_kernel(const int* __restrict__ target) {
    __shared__ unsigned short key16[CN_];
    __shared__ unsigned hist[1024];
    __shared__ float    cls[C_];
    __shared__ unsigned uns[8];
    __shared__ float    wsum[8];
    __shared__ float    s_pos;
    __shared__ unsigned sh_bin, sh_need;

    int tid = threadIdx.x;
    int wid = tid >> 5, lane = tid & 31;

    if (blockIdx.x >= B_) {
        int row = (int)(blockIdx.x - B_) * 256 + tid;
        float regv = 0.f;
        if (row < CN_) {
            float M = -3.0e38f;
            #pragma unroll
            for (int t = 0; t < 8; t++) M = fmaxf(M, g_pmax[row * 8 + t]);
            float S = 0.f;
            #pragma unroll
            for (int t = 0; t < 8; t++)
                S += g_psum[row * 8 + t] * __expf(g_pmax[row * 8 + t] - M);
            regv = M + __logf(S) - g_diag[row];
        }
        #pragma unroll
        for (int o = 16; o > 0; o >>= 1) regv += __shfl_xor_sync(0xffffffffu, regv, o);
        if (lane == 0 && regv != 0.f) atomicAdd(&g_acc[1], (double)regv);
        return;
    }

    int b = blockIdx.x;
    const float*  rowf = g_sim + (size_t)b * CN_;
    const float4* row4 = (const float4*)rowf;
    int tgt = target[b];

    for (int c = tid; c < C_; c += 256) cls[c] = 0.f;
    for (int i = tid; i < 1024; i += 256) hist[i] = 0;
    if (tid == 0) s_pos = 0.f;
    __syncthreads();

    // pass A: packed 16-bit prefixes + 1024-bin histogram + positive sum
    float pos = 0.f;
    for (int i = tid; i < CN_ / 4; i += 256) {
        float4 v = row4[i];
        unsigned pk0, pk1;
        if ((i >> 1) == tgt) {
            pos += v.x + v.y + v.z + v.w;
            pk0 = 0; pk1 = 0;
        } else {
            unsigned k0 = key_of(v.x), k1 = key_of(v.y), k2 = key_of(v.z), k3 = key_of(v.w);
            pk0 = (k0 >> 16) | (k1 & 0xFFFF0000u);
            pk1 = (k2 >> 16) | (k3 & 0xFFFF0000u);
            atomicAdd(&hist[k0 >> 22], 1u);
            atomicAdd(&hist[k1 >> 22], 1u);
            atomicAdd(&hist[k2 >> 22], 1u);
            atomicAdd(&hist[k3 >> 22], 1u);
        }
        *(uint2*)&key16[i * 4] = make_uint2(pk0, pk1);
    }
    if (pos != 0.f) atomicAdd(&s_pos, pos);
    __syncthreads();

    auto select_bin = [&](int nb, unsigned nd) {
        int nch = nb >> 3;
        unsigned chunk = 0;
        if (tid < nch) {
            int base = tid * 8;
            #pragma unroll
            for (int i = 0; i < 8; i++) chunk += hist[base + i];
        }
        unsigned v = chunk;
        #pragma unroll
        for (int off = 1; off < 32; off <<= 1) {
            unsigned t = __shfl_down_sync(0xffffffffu, v, off);
            if (lane + off < 32) v += t;
        }
        if (lane == 0) uns[wid] = v;
        __syncthreads();
        unsigned woff = 0;
        for (int w = wid + 1; w < 8; w++) woff += uns[w];
        unsigned Sincl = v + woff;
        unsigned Saft = Sincl - chunk;
        if (tid < nch && Saft < nd && Sincl >= nd) {
            unsigned cum = Saft;
            int bb = tid * 8 + 7;
            while (cum + hist[bb] < nd) { cum += hist[bb]; bb--; }
            sh_bin = (unsigned)bb;
            sh_need = nd - cum;
        }
        __syncthreads();
    };

    // level 0: 1024 bins over key16>>6
    select_bin(1024, NEED_);
    unsigned p0 = sh_bin;
    unsigned need = sh_need;
    __syncthreads();

    // level 1: 64 bins over key16&63 (smem-only scan)
    for (int i = tid; i < 64; i += 256) hist[i] = 0;
    __syncthreads();
    for (int i = tid; i < CN_ / 4; i += 256) {
        uint2 pk = *(const uint2*)&key16[i * 4];
        unsigned a0 = pk.x & 0xFFFFu, a1 = pk.x >> 16, a2 = pk.y & 0xFFFFu, a3 = pk.y >> 16;
        if ((a0 >> 6) == p0) atomicAdd(&hist[a0 & 63u], 1u);
        if ((a1 >> 6) == p0) atomicAdd(&hist[a1 & 63u], 1u);
        if ((a2 >> 6) == p0) atomicAdd(&hist[a2 & 63u], 1u);
        if ((a3 >> 6) == p0) atomicAdd(&hist[a3 & 63u], 1u);
    }
    __syncthreads();
    select_bin(64, need);
    unsigned p16 = (p0 << 6) | sh_bin;
    need = sh_need;
    __syncthreads();

    // pass B: accumulate sure-included (prefix > p16)
    for (int i = tid; i < CN_ / 4; i += 256) {
        if ((i >> 1) == tgt) continue;
        uint2 pk = *(const uint2*)&key16[i * 4];
        unsigned a0 = pk.x & 0xFFFFu, a1 = pk.x >> 16, a2 = pk.y & 0xFFFFu, a3 = pk.y >> 16;
        unsigned mx = max(max(a0, a1), max(a2, a3));
        if (mx <= p16) continue;
        float4 v = row4[i];
        float add = 0.f;
        if (a0 > p16) add += v.x;
        if (a1 > p16) add += v.y;
        if (a2 > p16) add += v.z;
        if (a3 > p16) add += v.w;
        if (add != 0.f) atomicAdd(&cls[i >> 1], add);
    }

    // level 2: 1024 bins over low-key bits [15:6], boundary elements only
    for (int i = tid; i < 1024; i += 256) hist[i] = 0;
    __syncthreads();
    for (int i = tid; i < CN_ / 4; i += 256) {
        uint2 pk = *(const uint2*)&key16[i * 4];
        unsigned a0 = pk.x & 0xFFFFu, a1 = pk.x >> 16, a2 = pk.y & 0xFFFFu, a3 = pk.y >> 16;
        int j = i * 4;
        if (a0 == p16) atomicAdd(&hist[(key_of(rowf[j]) >> 6) & 1023u], 1u);
        if (a1 == p16) atomicAdd(&hist[(key_of(rowf[j + 1]) >> 6) & 1023u], 1u);
        if (a2 == p16) atomicAdd(&hist[(key_of(rowf[j + 2]) >> 6) & 1023u], 1u);
        if (a3 == p16) atomicAdd(&hist[(key_of(rowf[j + 3]) >> 6) & 1023u], 1u);
    }
    __syncthreads();
    select_bin(1024, need);
    unsigned b2 = sh_bin;
    need = sh_need;
    __syncthreads();

    // level 3: 64 bins over bits [5:0]
    for (int i = tid; i < 64; i += 256) hist[i] = 0;
    __syncthreads();
    for (int i = tid; i < CN_ / 4; i += 256) {
        uint2 pk = *(const uint2*)&key16[i * 4];
        unsigned a0 = pk.x & 0xFFFFu, a1 = pk.x >> 16, a2 = pk.y & 0xFFFFu, a3 = pk.y >> 16;
        int j = i * 4;
        unsigned k;
        if (a0 == p16) { k = key_of(rowf[j]);     if (((k >> 6) & 1023u) == b2) atomicAdd(&hist[k & 63u], 1u); }
        if (a1 == p16) { k = key_of(rowf[j + 1]); if (((k >> 6) & 1023u) == b2) atomicAdd(&hist[k & 63u], 1u); }
        if (a2 == p16) { k = key_of(rowf[j + 2]); if (((k >> 6) & 1023u) == b2) atomicAdd(&hist[k & 63u], 1u); }
        if (a3 == p16) { k = key_of(rowf[j + 3]); if (((k >> 6) & 1023u) == b2) atomicAdd(&hist[k & 63u], 1u); }
    }
    __syncthreads();
    select_bin(64, need);
    unsigned T = (p16 << 16) | (b2 << 6) | sh_bin;
    __syncthreads();

    // boundary accumulate: key == p16 prefix and full key >= T
    for (int i = tid; i < CN_ / 4; i += 256) {
        uint2 pk = *(const uint2*)&key16[i * 4];
        unsigned a0 = pk.x & 0xFFFFu, a1 = pk.x >> 16, a2 = pk.y & 0xFFFFu, a3 = pk.y >> 16;
        if (a0 != p16 && a1 != p16 && a2 != p16 && a3 != p16) continue;
        int j = i * 4;
        float add = 0.f;
        if (a0 == p16) { float v = rowf[j];     if (key_of(v) >= T) add += v; }
        if (a1 == p16) { float v = rowf[j + 1]; if (key_of(v) >= T) add += v; }
        if (a2 == p16) { float v = rowf[j + 2]; if (key_of(v) >= T) add += v; }
        if (a3 == p16) { float v = rowf[j + 3]; if (key_of(v) >= T) add += v; }
        if (add != 0.f) atomicAdd(&cls[i >> 1], add);
    }
    __syncthreads();
    if (tid == 0) cls[tgt] += s_pos;
    __syncthreads();

    // masked softmax loss
    float lsum = 0.f;
    for (int c = tid; c < C_; c += 256) {
        float l = cls[c];
        if (l != 0.0f) lsum += __expf(l);
    }
    #pragma unroll
    for (int o = 16; o > 0; o >>= 1) lsum += __shfl_xor_sync(0xffffffffu, lsum, o);
    if (lane == 0) wsum[wid] = lsum;
    __syncthreads();
    if (tid == 0) {
        float tot = 0.f;
        #pragma unroll
        for (int w = 0; w < 8; w++) tot += wsum[w];
        float lt = cls[tgt];
        float num = (lt != 0.0f) ? __expf(lt) : 0.0f;
        float pr = num / (1e-8f + tot);
        atomicAdd(&g_acc[0], (double)(-__logf(pr + 1e-20f)));
    }
}

// ---------------- finalize ---------------------------------------------------
__global__ void finalize_kernel(float* out, int out_size) {
    double lc = g_acc[0] / (double)B_;
    double rg = g_acc[1] / (double)CN_;
    out[0] = (float)(lc + WLAMBDA * rg);
    if (out_size > 1) out[1] = (float)lc;
}

// ---------------- launch -----------------------------------------------------
extern "C" void kernel_launch(void* const* d_in, const int* in_sizes, int n_in,
                              void* d_out, int out_size) {
    const float* x       = (const float*)d_in[0];
    const float* proxies = (const float*)d_in[1];
    const int*   target  = (const int*)d_in[2];
    float* out = (float*)d_out;

    cudaFuncSetAttribute(gemm_all, cudaFuncAttributeMaxDynamicSharedMemorySize, DYN_SMEM);

    prep_x<<<B_ / 16, 256>>>(x);
    prep_prox<<<CN_ / 32, 256>>>(proxies);
    gemm_all<<<1008, 256, DYN_SMEM>>>();
    epilogue_kernel<<<B_ + (CN_ + 255) / 256, 256>>>(target);
    finalize_kernel<<<1, 1>>>(out, out_size);
}

// round 8
// speedup vs baseline: 1.4752x; 1.3839x over previous
#include <cuda_runtime.h>
#include <cuda_fp16.h>
#include <math.h>
#include <stdint.h>

// ---------------- problem constants ----------------------------------------
#define B_    1024
#define DIM_  512
#define C_    1000
#define N_    8
#define CN_   8000
#define CNP_  8064
#define NEED_ 392
#define WLAMBDA 0.3
#define KS32  32        // K / 16

// ---------------- scratch: fp16 fragment-major operand layouts ---------------
// A-layout uint4 [G=row/16][ks=K/16][q=lr(8)][lc(4)]:
//   halfs = A[r0][k0],A[r0][k0+1], A[r1][k0],A[r1][k0+1],
//           A[r0][k0+8],A[r0][k0+9], A[r1][k0+8],A[r1][k0+9]
//   (r0=16G+q, r1=r0+8, k0=16ks+2lc) -> uint4 = {a0,a1,a2,a3} of m16n8k16
// B-layout uint4 [GB=col/16][ks][qB=lr(8)][lc(4)]:
//   halfs = B'[n0][k0],B'[n0][k0+1], B'[n0][k0+8],B'[n0][k0+9],
//           B'[n1][k0],... (n0=16GB+qB, n1=n0+8) -> {b0,b1} for 2 col-groups
__device__ uint4  g_xrA[(size_t)(B_ / 16) * KS32 * 32];
__device__ uint4  g_pTA[(size_t)(CNP_ / 16) * KS32 * 32];
__device__ uint4  g_pTB[(size_t)(CNP_ / 16) * KS32 * 32];
__device__ uint4  g_ccB[(size_t)64 * KS32 * 32];
__device__ float  g_sim[(size_t)B_ * CN_];
__device__ float  g_pmax[CN_ * 8];
__device__ float  g_psum[CN_ * 8];
__device__ float  g_diag[CN_];
__device__ double g_acc[2];

// ---------------- helpers ----------------------------------------------------
__device__ __forceinline__ uint32_t h2u(float a, float b) {
    __half2 h = __floats2half2_rn(a, b);
    return *(uint32_t*)&h;
}
__device__ __forceinline__ uint32_t smem_u32(const void* p) {
    uint32_t a;
    asm("{ .reg .u64 t; cvta.to.shared.u64 t, %1; cvt.u32.u64 %0, t; }" : "=r"(a) : "l"(p));
    return a;
}
__device__ __forceinline__ void cpa16(uint32_t dst, const void* src) {
    uint64_t g = __cvta_generic_to_global(src);
    asm volatile("cp.async.cg.shared.global [%0], [%1], 16;" :: "r"(dst), "l"(g));
}
#define CP_COMMIT() asm volatile("cp.async.commit_group;" ::: "memory")

__device__ __forceinline__ void mma_f16(float* c, const uint4& a, uint32_t b0, uint32_t b1) {
    asm volatile(
        "mma.sync.aligned.m16n8k16.row.col.f32.f16.f16.f32 "
        "{%0,%1,%2,%3}, {%4,%5,%6,%7}, {%8,%9}, {%0,%1,%2,%3};"
        : "+f"(c[0]), "+f"(c[1]), "+f"(c[2]), "+f"(c[3])
        : "r"(a.x), "r"(a.y), "r"(a.z), "r"(a.w), "r"(b0), "r"(b1));
}
__device__ __forceinline__ unsigned key_of(float v) {
    unsigned u = __float_as_uint(v);
    return (u & 0x80000000u) ? ~u : (u | 0x80000000u);
}

// ---------------- prep: x -> fp16 A-layout -----------------------------------
__global__ void __launch_bounds__(256) prep_x(const float* __restrict__ x) {
    __shared__ float xs[16][520];
    int G = blockIdx.x, tid = threadIdx.x;
    if (G == 0 && tid < 2) g_acc[tid] = 0.0;

    const float4* x4 = (const float4*)x;
    #pragma unroll
    for (int e = 0; e < 8; e++) {
        int lin = e * 256 + tid;
        int row = lin >> 7, kf = lin & 127;
        float4 v = x4[(size_t)(G * 16 + row) * 128 + kf];
        xs[row][kf * 4 + 0] = v.x; xs[row][kf * 4 + 1] = v.y;
        xs[row][kf * 4 + 2] = v.z; xs[row][kf * 4 + 3] = v.w;
    }
    __syncthreads();
    #pragma unroll
    for (int e = 0; e < 4; e++) {
        int lin = e * 256 + tid;               // 1024 uint4
        int ks = lin >> 5, q = (lin >> 2) & 7, lc = lin & 3;
        int k0 = ks * 16 + lc * 2;
        uint4 o;
        o.x = h2u(xs[q][k0],     xs[q][k0 + 1]);
        o.y = h2u(xs[q + 8][k0], xs[q + 8][k0 + 1]);
        o.z = h2u(xs[q][k0 + 8], xs[q][k0 + 9]);
        o.w = h2u(xs[q + 8][k0 + 8], xs[q + 8][k0 + 9]);
        g_xrA[((size_t)G * KS32 + ks) * 32 + q * 4 + lc] = o;
    }
}

// ---------------- prep: proxies -> norms, pTA, pTB, ccB (fp16) ---------------
__global__ void __launch_bounds__(256) prep_prox(const float* __restrict__ proxies) {
    __shared__ float sinv[128];
    __shared__ float red2[256];
    int blk = blockIdx.x, tid = threadIdx.x;
    int j0 = blk * 128;

    // phase 1: column inverse norms
    {
        int col = tid & 127, half = tid >> 7;
        int j = j0 + col;
        float acc = 0.f;
        if (j < CN_) {
            for (int d = half * 256; d < half * 256 + 256; d++) {
                float v = proxies[(size_t)d * CN_ + j];
                acc += v * v;
            }
        }
        red2[tid] = acc;
    }
    __syncthreads();
    if (tid < 128) {
        float s = red2[tid] + red2[tid + 128];
        sinv[tid] = (j0 + tid < CN_) ? (1.0f / fmaxf(sqrtf(s), 1e-12f)) : 0.f;
    }
    __syncthreads();

    // phase 2: pTA (A-layout rows = proxy cols, k = d)
    #pragma unroll 4
    for (int e = 0; e < 32; e++) {
        int lin = e * 256 + tid;               // 8192
        int g = lin >> 10, ks = (lin >> 5) & 31, q = (lin >> 2) & 7, lc = lin & 3;
        int r0 = g * 16 + q, r1 = r0 + 8;
        int jg0 = j0 + r0, jg1 = j0 + r1;
        float iv0 = sinv[r0], iv1 = sinv[r1];
        int d0 = ks * 16 + lc * 2;
        float p00 = 0.f, p01 = 0.f, p10 = 0.f, p11 = 0.f;
        float p08 = 0.f, p09 = 0.f, p18 = 0.f, p19 = 0.f;
        if (jg0 < CN_) {
            p00 = proxies[(size_t)d0 * CN_ + jg0];
            p01 = proxies[(size_t)(d0 + 1) * CN_ + jg0];
            p08 = proxies[(size_t)(d0 + 8) * CN_ + jg0];
            p09 = proxies[(size_t)(d0 + 9) * CN_ + jg0];
        }
        if (jg1 < CN_) {
            p10 = proxies[(size_t)d0 * CN_ + jg1];
            p11 = proxies[(size_t)(d0 + 1) * CN_ + jg1];
            p18 = proxies[(size_t)(d0 + 8) * CN_ + jg1];
            p19 = proxies[(size_t)(d0 + 9) * CN_ + jg1];
        }
        uint4 o;
        o.x = h2u(p00 * iv0, p01 * iv0);
        o.y = h2u(p10 * iv1, p11 * iv1);
        o.z = h2u(p08 * iv0, p09 * iv0);
        o.w = h2u(p18 * iv1, p19 * iv1);
        g_pTA[((size_t)(j0 / 16 + g) * KS32 + ks) * 32 + q * 4 + lc] = o;
    }

    // phase 3: pTB (B-layout)
    #pragma unroll 4
    for (int e = 0; e < 32; e++) {
        int lin = e * 256 + tid;
        int gB = lin >> 10, ks = (lin >> 5) & 31, qB = (lin >> 2) & 7, lc = lin & 3;
        int r0 = gB * 16 + qB, r1 = r0 + 8;
        int n0 = j0 + r0, n1 = j0 + r1;
        float iv0 = sinv[r0], iv1 = sinv[r1];
        int k0 = ks * 16 + lc * 2;
        float q00 = 0.f, q01 = 0.f, q08 = 0.f, q09 = 0.f;
        float q10 = 0.f, q11 = 0.f, q18 = 0.f, q19 = 0.f;
        if (n0 < CN_) {
            q00 = proxies[(size_t)k0 * CN_ + n0];
            q01 = proxies[(size_t)(k0 + 1) * CN_ + n0];
            q08 = proxies[(size_t)(k0 + 8) * CN_ + n0];
            q09 = proxies[(size_t)(k0 + 9) * CN_ + n0];
        }
        if (n1 < CN_) {
            q10 = proxies[(size_t)k0 * CN_ + n1];
            q11 = proxies[(size_t)(k0 + 1) * CN_ + n1];
            q18 = proxies[(size_t)(k0 + 8) * CN_ + n1];
            q19 = proxies[(size_t)(k0 + 9) * CN_ + n1];
        }
        uint4 o;
        o.x = h2u(q00 * iv0, q01 * iv0);
        o.y = h2u(q08 * iv0, q09 * iv0);
        o.z = h2u(q10 * iv1, q11 * iv1);
        o.w = h2u(q18 * iv1, q19 * iv1);
        g_pTB[((size_t)(j0 / 16 + gB) * KS32 + ks) * 32 + qB * 4 + lc] = o;
    }

    // phase 4: ccB (class sums, B-layout; classes blk*16 .. +15)
    #pragma unroll
    for (int e = 0; e < 4; e++) {
        int lin = e * 256 + tid;               // 1024
        int ks = lin >> 5, qB = (lin >> 2) & 7, lc = lin & 3;
        int ca = blk * 16 + qB, cb = ca + 8;
        int k0 = ks * 16 + lc * 2;
        float a0 = 0.f, a1 = 0.f, a8 = 0.f, a9 = 0.f;
        float b0 = 0.f, b1 = 0.f, b8 = 0.f, b9 = 0.f;
        if (ca < C_) {
            #pragma unroll
            for (int n = 0; n < 8; n++) {
                int j = ca * 8 + n;
                float iv = sinv[j - j0];
                a0 += proxies[(size_t)k0 * CN_ + j] * iv;
                a1 += proxies[(size_t)(k0 + 1) * CN_ + j] * iv;
                a8 += proxies[(size_t)(k0 + 8) * CN_ + j] * iv;
                a9 += proxies[(size_t)(k0 + 9) * CN_ + j] * iv;
            }
        }
        if (cb < C_) {
            #pragma unroll
            for (int n = 0; n < 8; n++) {
                int j = cb * 8 + n;
                float iv = sinv[j - j0];
                b0 += proxies[(size_t)k0 * CN_ + j] * iv;
                b1 += proxies[(size_t)(k0 + 1) * CN_ + j] * iv;
                b8 += proxies[(size_t)(k0 + 8) * CN_ + j] * iv;
                b9 += proxies[(size_t)(k0 + 9) * CN_ + j] * iv;
            }
        }
        uint4 o;
        o.x = h2u(a0, a1);
        o.y = h2u(a8, a9);
        o.z = h2u(b0, b1);
        o.w = h2u(b8, b9);
        g_ccB[((size_t)blk * KS32 + ks) * 32 + qB * 4 + lc] = o;
    }
}

// ---------------- merged fp16 m16n8k16 GEMM (3-stage, 2 CTA/SM) --------------
#define NCHUNK 8            // chunks of K=64
#define STG 32768           // 16KB A + 16KB B per stage
#define DYN_SMEM (3 * STG)
#define TP 130

__global__ void __launch_bounds__(256, 2) gemm_all() {
    extern __shared__ char sh[];
    int bid = blockIdx.x;
    const uint4 *Ag, *Bg;
    int bm, bn;
    bool mode1 = (bid >= 504);
    if (!mode1) {
        Ag = g_xrA; Bg = g_pTB;
        bn = (bid % 63) * 128; bm = (bid / 63) * 128;
    } else {
        int b2 = bid - 504;
        Ag = g_pTA; Bg = g_ccB;
        bn = (b2 & 7) * 128; bm = (b2 >> 3) * 128;
    }
    int tid = threadIdx.x, wid = tid >> 5, lane = tid & 31;
    int lr = lane >> 2, lc4 = lane & 3;
    uint32_t sb = smem_u32(sh);
    int GA0 = bm / 16, GB0 = bn / 16;

    auto load_stage = [&](int ch, int s) {
        uint32_t stage = sb + (uint32_t)s * STG;
        #pragma unroll
        for (int e = 0; e < 8; e++) {
            int lin = e * 256 + tid;
            if (lin < 1024) {
                int ks = lin >> 8, g = (lin >> 5) & 7, q = (lin >> 2) & 7, lc = lin & 3;
                cpa16(stage + (uint32_t)lin * 16,
                      Ag + ((size_t)(GA0 + g) * KS32 + ch * 4 + ks) * 32 + q * 4 + lc);
            } else {
                int l2 = lin - 1024;
                int ks = l2 >> 8, gB = (l2 >> 5) & 7, qB = (l2 >> 2) & 7, lc = l2 & 3;
                cpa16(stage + 16384u + (uint32_t)l2 * 16,
                      Bg + ((size_t)(GB0 + gB) * KS32 + ch * 4 + ks) * 32 + qB * 4 + lc);
            }
        }
        CP_COMMIT();
    };

    load_stage(0, 0);
    load_stage(1, 1);

    int ga = (wid >> 2) * 4;    // A group base (4 groups of 16 rows = 64)
    int gb2 = (wid & 3) * 2;    // B group base (2 groups of 16 cols = 32)

    float c[4][4][4];
    #pragma unroll
    for (int mt = 0; mt < 4; mt++)
        #pragma unroll
        for (int nt = 0; nt < 4; nt++)
            #pragma unroll
            for (int i = 0; i < 4; i++) c[mt][nt][i] = 0.f;

    for (int ch = 0; ch < NCHUNK; ch++) {
        if (ch < NCHUNK - 1) asm volatile("cp.async.wait_group 1;" ::: "memory");
        else                 asm volatile("cp.async.wait_group 0;" ::: "memory");
        __syncthreads();

        if (ch + 2 < NCHUNK) load_stage(ch + 2, (ch + 2) % 3);

        const uint4* As = (const uint4*)(sh + (ch % 3) * STG);
        const uint4* Bs = (const uint4*)(sh + (ch % 3) * STG + 16384);

        #pragma unroll
        for (int ks = 0; ks < 4; ks++) {
            uint4 va[4], vb[2];
            #pragma unroll
            for (int mt = 0; mt < 4; mt++)
                va[mt] = As[((ks * 8 + ga + mt) * 8 + lr) * 4 + lc4];
            #pragma unroll
            for (int u = 0; u < 2; u++)
                vb[u] = Bs[((ks * 8 + gb2 + u) * 8 + lr) * 4 + lc4];
            #pragma unroll
            for (int mt = 0; mt < 4; mt++) {
                mma_f16(c[mt][0], va[mt], vb[0].x, vb[0].y);
                mma_f16(c[mt][1], va[mt], vb[0].z, vb[0].w);
                mma_f16(c[mt][2], va[mt], vb[1].x, vb[1].y);
                mma_f16(c[mt][3], va[mt], vb[1].z, vb[1].w);
            }
        }
    }

    int wm = (wid >> 2) * 64, wn = (wid & 3) * 32;

    if (!mode1) {
        #pragma unroll
        for (int mt = 0; mt < 4; mt++) {
            int row = bm + wm + mt * 16 + lr;
            #pragma unroll
            for (int nt = 0; nt < 4; nt++) {
                int col = bn + wn + nt * 8 + lc4 * 2;
                if (col < CN_) {
                    *(float2*)(g_sim + (size_t)row * CN_ + col) = make_float2(c[mt][nt][0], c[mt][nt][1]);
                    *(float2*)(g_sim + (size_t)(row + 8) * CN_ + col) = make_float2(c[mt][nt][2], c[mt][nt][3]);
                }
            }
        }
        return;
    }

    // ---- mode 1: dump to smem tile, reduce rows to lse partials + diag ----
    __syncthreads();
    float* tile = (float*)sh;
    #pragma unroll
    for (int mt = 0; mt < 4; mt++) {
        int r0 = wm + mt * 16 + lr;
        #pragma unroll
        for (int nt = 0; nt < 4; nt++) {
            int cc = wn + nt * 8 + lc4 * 2;
            *(float2*)&tile[r0 * TP + cc] = make_float2(c[mt][nt][0], c[mt][nt][1]);
            *(float2*)&tile[(r0 + 8) * TP + cc] = make_float2(c[mt][nt][2], c[mt][nt][3]);
        }
    }
    __syncthreads();

    {
        int r = tid >> 1, h = tid & 1;
        int gr = bm + r;
        int vcols = C_ - bn; if (vcols > 128) vcols = 128;
        int cA = h * 64;
        int cB = cA + 64; if (cB > vcols) cB = vcols;
        float m = -3.0e38f;
        for (int j = cA; j < cB; j++) m = fmaxf(m, tile[r * TP + j]);
        float s = 0.f;
        for (int j = cA; j < cB; j++) s += __expf(tile[r * TP + j] - m);
        float mo = __shfl_xor_sync(0xffffffffu, m, 1);
        float so = __shfl_xor_sync(0xffffffffu, s, 1);
        float M = fmaxf(m, mo);
        float S = s * __expf(m - M) + so * __expf(mo - M);
        if (h == 0 && gr < CN_) {
            g_pmax[gr * 8 + (bn >> 7)] = M;
            g_psum[gr * 8 + (bn >> 7)] = S;
            int cl = gr >> 3;
            if (cl >= bn && cl - bn < vcols) g_diag[gr] = tile[r * TP + (cl - bn)];
        }
    }
}

// ---------------- epilogue: topk+loss (blocks <1024), lse combine (rest) -----
__global__ void __launch_bounds__(256) epilogue_kernel(const int* __restrict__ target) {
    __shared__ unsigned short key16[CN_];
    __shared__ unsigned hist[1024];
    __shared__ float    cls[C_];
    __shared__ unsigned uns[8];
    __shared__ float    wsum[8];
    __shared__ float    s_pos;
    __shared__ unsigned sh_bin, sh_need;

    int tid = threadIdx.x;
    int wid = tid >> 5, lane = tid & 31;

    if (blockIdx.x >= B_) {
        int row = (int)(blockIdx.x - B_) * 256 + tid;
        float regv = 0.f;
        if (row < CN_) {
            float M = -3.0e38f;
            #pragma unroll
            for (int t = 0; t < 8; t++) M = fmaxf(M, g_pmax[row * 8 + t]);
            float S = 0.f;
            #pragma unroll
            for (int t = 0; t < 8; t++)
                S += g_psum[row * 8 + t] * __expf(g_pmax[row * 8 + t] - M);
            regv = M + __logf(S) - g_diag[row];
        }
        #pragma unroll
        for (int o = 16; o > 0; o >>= 1) regv += __shfl_xor_sync(0xffffffffu, regv, o);
        if (lane == 0 && regv != 0.f) atomicAdd(&g_acc[1], (double)regv);
        return;
    }

    int b = blockIdx.x;
    const float*  rowf = g_sim + (size_t)b * CN_;
    const float4* row4 = (const float4*)rowf;
    int tgt = target[b];

    for (int c = tid; c < C_; c += 256) cls[c] = 0.f;
    for (int i = tid; i < 1024; i += 256) hist[i] = 0;
    if (tid == 0) s_pos = 0.f;
    __syncthreads();

    float pos = 0.f;
    for (int i = tid; i < CN_ / 4; i += 256) {
        float4 v = row4[i];
        unsigned pk0, pk1;
        if ((i >> 1) == tgt) {
            pos += v.x + v.y + v.z + v.w;
            pk0 = 0; pk1 = 0;
        } else {
            unsigned k0 = key_of(v.x), k1 = key_of(v.y), k2 = key_of(v.z), k3 = key_of(v.w);
            pk0 = (k0 >> 16) | (k1 & 0xFFFF0000u);
            pk1 = (k2 >> 16) | (k3 & 0xFFFF0000u);
            atomicAdd(&hist[k0 >> 22], 1u);
            atomicAdd(&hist[k1 >> 22], 1u);
            atomicAdd(&hist[k2 >> 22], 1u);
            atomicAdd(&hist[k3 >> 22], 1u);
        }
        *(uint2*)&key16[i * 4] = make_uint2(pk0, pk1);
    }
    if (pos != 0.f) atomicAdd(&s_pos, pos);
    __syncthreads();

    auto select_bin = [&](int nb, unsigned nd) {
        int nch = nb >> 3;
        unsigned chunk = 0;
        if (tid < nch) {
            int base = tid * 8;
            #pragma unroll
            for (int i = 0; i < 8; i++) chunk += hist[base + i];
        }
        unsigned v = chunk;
        #pragma unroll
        for (int off = 1; off < 32; off <<= 1) {
            unsigned t = __shfl_down_sync(0xffffffffu, v, off);
            if (lane + off < 32) v += t;
        }
        if (lane == 0) uns[wid] = v;
        __syncthreads();
        unsigned woff = 0;
        for (int w = wid + 1; w < 8; w++) woff += uns[w];
        unsigned Sincl = v + woff;
        unsigned Saft = Sincl - chunk;
        if (tid < nch && Saft < nd && Sincl >= nd) {
            unsigned cum = Saft;
            int bb = tid * 8 + 7;
            while (cum + hist[bb] < nd) { cum += hist[bb]; bb--; }
            sh_bin = (unsigned)bb;
            sh_need = nd - cum;
        }
        __syncthreads();
    };

    select_bin(1024, NEED_);
    unsigned p0 = sh_bin;
    unsigned need = sh_need;
    __syncthreads();

    for (int i = tid; i < 64; i += 256) hist[i] = 0;
    __syncthreads();
    for (int i = tid; i < CN_ / 4; i += 256) {
        uint2 pk = *(const uint2*)&key16[i * 4];
        unsigned a0 = pk.x & 0xFFFFu, a1 = pk.x >> 16, a2 = pk.y & 0xFFFFu, a3 = pk.y >> 16;
        if ((a0 >> 6) == p0) atomicAdd(&hist[a0 & 63u], 1u);
        if ((a1 >> 6) == p0) atomicAdd(&hist[a1 & 63u], 1u);
        if ((a2 >> 6) == p0) atomicAdd(&hist[a2 & 63u], 1u);
        if ((a3 >> 6) == p0) atomicAdd(&hist[a3 & 63u], 1u);
    }
    __syncthreads();
    select_bin(64, need);
    unsigned p16 = (p0 << 6) | sh_bin;
    need = sh_need;
    __syncthreads();

    for (int i = tid; i < CN_ / 4; i += 256) {
        if ((i >> 1) == tgt) continue;
        uint2 pk = *(const uint2*)&key16[i * 4];
        unsigned a0 = pk.x & 0xFFFFu, a1 = pk.x >> 16, a2 = pk.y & 0xFFFFu, a3 = pk.y >> 16;
        unsigned mx = max(max(a0, a1), max(a2, a3));
        if (mx <= p16) continue;
        float4 v = row4[i];
        float add = 0.f;
        if (a0 > p16) add += v.x;
        if (a1 > p16) add += v.y;
        if (a2 > p16) add += v.z;
        if (a3 > p16) add += v.w;
        if (add != 0.f) atomicAdd(&cls[i >> 1], add);
    }

    for (int i = tid; i < 1024; i += 256) hist[i] = 0;
    __syncthreads();
    for (int i = tid; i < CN_ / 4; i += 256) {
        uint2 pk = *(const uint2*)&key16[i * 4];
        unsigned a0 = pk.x & 0xFFFFu, a1 = pk.x >> 16, a2 = pk.y & 0xFFFFu, a3 = pk.y >> 16;
        int j = i * 4;
        if (a0 == p16) atomicAdd(&hist[(key_of(rowf[j]) >> 6) & 1023u], 1u);
        if (a1 == p16) atomicAdd(&hist[(key_of(rowf[j + 1]) >> 6) & 1023u], 1u);
        if (a2 == p16) atomicAdd(&hist[(key_of(rowf[j + 2]) >> 6) & 1023u], 1u);
        if (a3 == p16) atomicAdd(&hist[(key_of(rowf[j + 3]) >> 6) & 1023u], 1u);
    }
    __syncthreads();
    select_bin(1024, need);
    unsigned b2 = sh_bin;
    need = sh_need;
    __syncthreads();

    for (int i = tid; i < 64; i += 256) hist[i] = 0;
    __syncthreads();
    for (int i = tid; i < CN_ / 4; i += 256) {
        uint2 pk = *(const uint2*)&key16[i * 4];
        unsigned a0 = pk.x & 0xFFFFu, a1 = pk.x >> 16, a2 = pk.y & 0xFFFFu, a3 = pk.y >> 16;
        int j = i * 4;
        unsigned k;
        if (a0 == p16) { k = key_of(rowf[j]);     if (((k >> 6) & 1023u) == b2) atomicAdd(&hist[k & 63u], 1u); }
        if (a1 == p16) { k = key_of(rowf[j + 1]); if (((k >> 6) & 1023u) == b2) atomicAdd(&hist[k & 63u], 1u); }
        if (a2 == p16) { k = key_of(rowf[j + 2]); if (((k >> 6) & 1023u) == b2) atomicAdd(&hist[k & 63u], 1u); }
        if (a3 == p16) { k = key_of(rowf[j + 3]); if (((k >> 6) & 1023u) == b2) atomicAdd(&hist[k & 63u], 1u); }
    }
    __syncthreads();
    select_bin(64, need);
    unsigned T = (p16 << 16) | (b2 << 6) | sh_bin;
    __syncthreads();

    for (int i = tid; i < CN_ / 4; i += 256) {
        uint2 pk = *(const uint2*)&key16[i * 4];
        unsigned a0 = pk.x & 0xFFFFu, a1 = pk.x >> 16, a2 = pk.y & 0xFFFFu, a3 = pk.y >> 16;
        if (a0 != p16 && a1 != p16 && a2 != p16 && a3 != p16) continue;
        int j = i * 4;
        float add = 0.f;
        if (a0 == p16) { float v = rowf[j];     if (key_of(v) >= T) add += v; }
        if (a1 == p16) { float v = rowf[j + 1]; if (key_of(v) >= T) add += v; }
        if (a2 == p16) { float v = rowf[j + 2]; if (key_of(v) >= T) add += v; }
        if (a3 == p16) { float v = rowf[j + 3]; if (key_of(v) >= T) add += v; }
        if (add != 0.f) atomicAdd(&cls[i >> 1], add);
    }
    __syncthreads();
    if (tid == 0) cls[tgt] += s_pos;
    __syncthreads();

    float lsum = 0.f;
    for (int c = tid; c < C_; c += 256) {
        float l = cls[c];
        if (l != 0.0f) lsum += __expf(l);
    }
    #pragma unroll
    for (int o = 16; o > 0; o >>= 1) lsum += __shfl_xor_sync(0xffffffffu, lsum, o);
    if (lane == 0) wsum[wid] = lsum;
    __syncthreads();
    if (tid == 0) {
        float tot = 0.f;
        #pragma unroll
        for (int w = 0; w < 8; w++) tot += wsum[w];
        float lt = cls[tgt];
        float num = (lt != 0.0f) ? __expf(lt) : 0.0f;
        float pr = num / (1e-8f + tot);
        atomicAdd(&g_acc[0], (double)(-__logf(pr + 1e-20f)));
    }
}

// ---------------- finalize ---------------------------------------------------
__global__ void finalize_kernel(float* out, int out_size) {
    double lc = g_acc[0] / (double)B_;
    double rg = g_acc[1] / (double)CN_;
    out[0] = (float)(lc + WLAMBDA * rg);
    if (out_size > 1) out[1] = (float)lc;
}

// ---------------- launch -----------------------------------------------------
extern "C" void kernel_launch(void* const* d_in, const int* in_sizes, int n_in,
                              void* d_out, int out_size) {
    const float* x       = (const float*)d_in[0];
    const float* proxies = (const float*)d_in[1];
    const int*   target  = (const int*)d_in[2];
    float* out = (float*)d_out;

    cudaFuncSetAttribute(gemm_all, cudaFuncAttributeMaxDynamicSharedMemorySize, DYN_SMEM);

    prep_x<<<B_ / 16, 256>>>(x);
    prep_prox<<<CNP_ / 128, 256>>>(proxies);
    gemm_all<<<1008, 256, DYN_SMEM>>>();
    epilogue_kernel<<<B_ + (CN_ + 255) / 256, 256>>>(target);
    finalize_kernel<<<1, 1>>>(out, out_size);
}